// round 12
// baseline (speedup 1.0000x reference)
#include <cuda_runtime.h>
#include <cuda_bf16.h>
#include <cstdint>

#define Bn   16384
#define INn  512
#define Hn   1024
#define OUTn 512
#define Mn   8
#define Rn   256
#define CYC  4

// ---------------- scratch (static device globals; no runtime allocation) ----
__device__ float g_h   [(size_t)Bn * Hn];            // 64 MB
__device__ float g_r   [(size_t)Bn * Hn];            // 64 MB router features
__device__ float g_probs[(size_t)Bn * CYC * Mn];     // 2 MB
__device__ float g_wr1c[(size_t)Hn * Hn];            // 4 MB
__device__ __nv_bfloat16 g_ahA[(size_t)Bn * Hn];     // 32 MB  A hi plane (row-major [b][k])
__device__ __nv_bfloat16 g_alA[(size_t)Bn * Hn];     // 32 MB  A lo plane
__device__ __nv_bfloat16 g_ahB[(size_t)Bn * Hn];     // 32 MB  ping-pong
__device__ __nv_bfloat16 g_alB[(size_t)Bn * Hn];     // 32 MB
__device__ __nv_bfloat16 g_wh[(size_t)Mn * Hn * Hn]; // 16 MB W_mod^T hi [m][n][k]
__device__ __nv_bfloat16 g_wl[(size_t)Mn * Hn * Hn]; // 16 MB W_mod^T lo

// ---------------- helpers ---------------------------------------------------
__device__ __forceinline__ void bsplit(float x, __nv_bfloat16& h, __nv_bfloat16& l) {
    h = __float2bfloat16(x);
    l = __float2bfloat16(x - __bfloat162float(h));
}

__device__ __forceinline__ void mma_bf16(float* c, const uint32_t* a, const uint32_t* b) {
    asm volatile(
        "mma.sync.aligned.m16n8k16.row.col.f32.bf16.bf16.f32 "
        "{%0,%1,%2,%3}, {%4,%5,%6,%7}, {%8,%9}, {%0,%1,%2,%3};\n"
        : "+f"(c[0]), "+f"(c[1]), "+f"(c[2]), "+f"(c[3])
        : "r"(a[0]), "r"(a[1]), "r"(a[2]), "r"(a[3]), "r"(b[0]), "r"(b[1]));
}

__device__ __forceinline__ void ldsm4(uint32_t* r, uint32_t a) {
    asm volatile("ldmatrix.sync.aligned.m8n8.x4.shared.b16 {%0,%1,%2,%3}, [%4];\n"
        : "=r"(r[0]), "=r"(r[1]), "=r"(r[2]), "=r"(r[3]) : "r"(a));
}

__device__ __forceinline__ void cp16(uint32_t dst, const void* src) {
    asm volatile("cp.async.cg.shared.global [%0], [%1], 16;\n" :: "r"(dst), "l"(src));
}
#define CP_COMMIT() asm volatile("cp.async.commit_group;\n" ::: "memory")
#define CP_WAIT1()  asm volatile("cp.async.wait_group 1;\n" ::: "memory")
#define CP_WAIT0()  asm volatile("cp.async.wait_group 0;\n" ::: "memory")

// split 8 floats into packed bf16 hi/lo 16B vectors
__device__ __forceinline__ void split8(const float* v, uint4& H, uint4& L) {
    uint32_t h[4], l[4];
#pragma unroll
    for (int q = 0; q < 4; q++) {
        __nv_bfloat16 h0 = __float2bfloat16(v[2*q]);
        __nv_bfloat16 h1 = __float2bfloat16(v[2*q+1]);
        __nv_bfloat16 l0 = __float2bfloat16(v[2*q]   - __bfloat162float(h0));
        __nv_bfloat16 l1 = __float2bfloat16(v[2*q+1] - __bfloat162float(h1));
        __nv_bfloat162 hh = __halves2bfloat162(h0, h1);
        __nv_bfloat162 ll = __halves2bfloat162(l0, l1);
        h[q] = *reinterpret_cast<uint32_t*>(&hh);
        l[q] = *reinterpret_cast<uint32_t*>(&ll);
    }
    H = make_uint4(h[0], h[1], h[2], h[3]);
    L = make_uint4(l[0], l[1], l[2], l[3]);
}

// ======================= pipelined expert kernel (16 warps) =================
#define PLANE   5120                 // 128 rows * 40 elems per plane
#define STAGEE  (4 * PLANE)          // elems per stage (Ah,Al,Bh,Bl)
#define STAGEB  (STAGEE * 2)         // 40960 bytes
#define OSM_OFF (3 * STAGEB)         // 122880
#define OSM_STR 132                  // fp32 stride (multiple of 4)
#define SMEM_TOT (OSM_OFF + 128 * OSM_STR * 4)   // 122880 + 67584 = 190464
#define NIT     (Mn * 32)            // 256 iterations: 8 experts x 32 ktiles
#define ETHR    512                  // expert kernel threads (16 warps)

// copy one 128x32 ktile of A(hi/lo) + B(hi/lo) planes into a smem stage (512 thr)
__device__ __forceinline__ void stage_load(
    __nv_bfloat16* smstage,
    const __nv_bfloat16* __restrict__ Ah, const __nv_bfloat16* __restrict__ Al,
    const __nv_bfloat16* __restrict__ Bh, const __nv_bfloat16* __restrict__ Bl,
    int tid) {
    int row = tid >> 2;            // 0..127
    int c   = (tid & 3) * 8;       // 0,8,16,24
    uint32_t base = (uint32_t)__cvta_generic_to_shared(smstage);
    uint32_t d = base + (uint32_t)(row * 40 + c) * 2;
    size_t go = (size_t)row * Hn + c;
    cp16(d,                  Ah + go);
    cp16(d + PLANE * 2,      Al + go);
    cp16(d + 2 * PLANE * 2,  Bh + go);
    cp16(d + 3 * PLANE * 2,  Bl + go);
}

// one 32-k tile of bf16x3 mma (AhBh + AhBl + AlBh), 32x32 warp tile
__device__ __forceinline__ void ktile_mma(const __nv_bfloat16* smstage,
                                          float c[2][4][4], int wm, int wn, int lane) {
    uint32_t base = (uint32_t)__cvta_generic_to_shared(smstage);
    int r  = lane & 15;
    int cb = (lane >> 4) * 8;
#pragma unroll
    for (int kk = 0; kk < 32; kk += 16) {
        uint32_t ah[2][4], al[2][4], bh[4][2], bl[4][2];
#pragma unroll
        for (int im = 0; im < 2; im++) {
            uint32_t a = base + (uint32_t)((wm + im * 16 + r) * 40 + kk + cb) * 2;
            ldsm4(ah[im], a);
            ldsm4(al[im], a + PLANE * 2);
        }
#pragma unroll
        for (int p = 0; p < 2; p++) {
            uint32_t b = base + (uint32_t)(2 * PLANE + (wn + p * 16 + r) * 40 + kk + cb) * 2;
            uint32_t t[4];
            ldsm4(t, b);
            bh[2 * p][0] = t[0]; bh[2 * p][1] = t[2];
            bh[2 * p + 1][0] = t[1]; bh[2 * p + 1][1] = t[3];
            ldsm4(t, b + PLANE * 2);
            bl[2 * p][0] = t[0]; bl[2 * p][1] = t[2];
            bl[2 * p + 1][0] = t[1]; bl[2 * p + 1][1] = t[3];
        }
#pragma unroll
        for (int in = 0; in < 4; in++)
#pragma unroll
            for (int im = 0; im < 2; im++) {
                mma_bf16(c[im][in], ah[im], bh[in]);
                mma_bf16(c[im][in], ah[im], bl[in]);
                mma_bf16(c[im][in], al[im], bh[in]);
            }
    }
}

// dst = sum_m probs[.,cyc,m] * relu(src @ W_mod[m] + b_mod[m]); emits next-cycle
// bf16 hi/lo planes, and fp32 h when wf32 != 0. Mixture accumulator in smem.
__global__ void __launch_bounds__(ETHR, 1) expert_pl(
    const __nv_bfloat16* __restrict__ Ah, const __nv_bfloat16* __restrict__ Al,
    const __nv_bfloat16* __restrict__ Wh, const __nv_bfloat16* __restrict__ Wl,
    __nv_bfloat16* __restrict__ Oh, __nv_bfloat16* __restrict__ Ol,
    float* __restrict__ dstf, int wf32,
    const float* __restrict__ bmod, const float* __restrict__ probs, int cyc) {
    extern __shared__ char smem[];
    __nv_bfloat16* stg = reinterpret_cast<__nv_bfloat16*>(smem);
    float* o_f = reinterpret_cast<float*>(smem + OSM_OFF);
    int tid = threadIdx.x, lane = tid & 31, wid = tid >> 5;
    int wm = (wid & 3) * 32, wn = (wid >> 2) * 32;   // 4x4 warp grid, 32x32 tiles
    int bR = blockIdx.y * 128, bC = blockIdx.x * 128;
    int qr = lane >> 2, qc2 = (lane & 3) << 1;

    for (int i = tid; i < 128 * OSM_STR; i += ETHR) o_f[i] = 0.f;

    const __nv_bfloat16* Ab_h = Ah + (size_t)bR * Hn;
    const __nv_bfloat16* Ab_l = Al + (size_t)bR * Hn;
    const __nv_bfloat16* Bb_h = Wh + (size_t)bC * Hn;
    const __nv_bfloat16* Bb_l = Wl + (size_t)bC * Hn;

    // stage s: expert m = s>>5, ktile t = s&31
    auto ld_stage = [&](int s) {
        int m = s >> 5, t = s & 31;
        size_t boff = (size_t)m * Hn * Hn + (size_t)t * 32;
        stage_load(stg + (s % 3) * STAGEE,
                   Ab_h + t * 32, Ab_l + t * 32,
                   Bb_h + boff, Bb_l + boff, tid);
    };
    ld_stage(0); CP_COMMIT();
    ld_stage(1); CP_COMMIT();

    float c[2][4][4];
#pragma unroll
    for (int i = 0; i < 2; i++)
#pragma unroll
        for (int j = 0; j < 4; j++)
#pragma unroll
            for (int q = 0; q < 4; q++) c[i][j][q] = 0.f;

    for (int it = 0; it < NIT; it++) {
        if (it < NIT - 1) CP_WAIT1(); else CP_WAIT0();
        __syncthreads();
        int nxt = it + 2;
        if (nxt < NIT) { ld_stage(nxt); CP_COMMIT(); }

        ktile_mma(stg + (it % 3) * STAGEE, c, wm, wn, lane);

        if ((it & 31) == 31) {            // end of expert m: fold into smem o
            int m = it >> 5;
#pragma unroll
            for (int im = 0; im < 2; im++) {
                int r0 = wm + im * 16 + qr;
                int gr = bR + r0;
                float p0 = probs[((size_t)gr * CYC + cyc) * Mn + m];
                float p8 = probs[((size_t)(gr + 8) * CYC + cyc) * Mn + m];
#pragma unroll
                for (int in = 0; in < 4; in++) {
                    int col = wn + in * 8 + qc2;
                    float2 bv = *reinterpret_cast<const float2*>(&bmod[(size_t)m * Hn + bC + col]);
                    float2* s0 = reinterpret_cast<float2*>(&o_f[r0 * OSM_STR + col]);
                    float2* s8 = reinterpret_cast<float2*>(&o_f[(r0 + 8) * OSM_STR + col]);
                    float2 v0 = *s0, v8 = *s8;
                    v0.x += p0 * fmaxf(c[im][in][0] + bv.x, 0.f);
                    v0.y += p0 * fmaxf(c[im][in][1] + bv.y, 0.f);
                    v8.x += p8 * fmaxf(c[im][in][2] + bv.x, 0.f);
                    v8.y += p8 * fmaxf(c[im][in][3] + bv.y, 0.f);
                    *s0 = v0; *s8 = v8;
                    c[im][in][0] = 0.f; c[im][in][1] = 0.f;
                    c[im][in][2] = 0.f; c[im][in][3] = 0.f;
                }
            }
        }
    }
    __syncthreads();

    // coalesced epilogue: write next-cycle planes (+ fp32 h on last cycle)
    int row = tid >> 2, cs = (tid & 3) * 32;
    int gr = bR + row;
    size_t goff = (size_t)gr * Hn + bC + cs;
#pragma unroll
    for (int u = 0; u < 4; u++) {
        float4 a0 = *reinterpret_cast<float4*>(&o_f[row * OSM_STR + cs + u * 8]);
        float4 a1 = *reinterpret_cast<float4*>(&o_f[row * OSM_STR + cs + u * 8 + 4]);
        float v[8] = {a0.x, a0.y, a0.z, a0.w, a1.x, a1.y, a1.z, a1.w};
        uint4 H, L;
        split8(v, H, L);
        *reinterpret_cast<uint4*>(Oh + goff + u * 8) = H;
        *reinterpret_cast<uint4*>(Ol + goff + u * 8) = L;
        if (wf32) {
            *reinterpret_cast<float4*>(dstf + goff + u * 8)     = a0;
            *reinterpret_cast<float4*>(dstf + goff + u * 8 + 4) = a1;
        }
    }
}

// ======================= conversion kernels =================================
// h (fp32) -> hi/lo bf16 planes, row-major [b][k]
__global__ void __launch_bounds__(256) hconv(const float4* __restrict__ src,
                                             uint2* __restrict__ hdst,
                                             uint2* __restrict__ ldst) {
    size_t i = (size_t)blockIdx.x * 256 + threadIdx.x;
    float4 v = src[i];
    __nv_bfloat16 h0, h1, h2, h3, l0, l1, l2, l3;
    bsplit(v.x, h0, l0); bsplit(v.y, h1, l1);
    bsplit(v.z, h2, l2); bsplit(v.w, h3, l3);
    __nv_bfloat162 H0 = __halves2bfloat162(h0, h1), H1 = __halves2bfloat162(h2, h3);
    __nv_bfloat162 L0 = __halves2bfloat162(l0, l1), L1 = __halves2bfloat162(l2, l3);
    uint2 H, L;
    H.x = *reinterpret_cast<uint32_t*>(&H0); H.y = *reinterpret_cast<uint32_t*>(&H1);
    L.x = *reinterpret_cast<uint32_t*>(&L0); L.y = *reinterpret_cast<uint32_t*>(&L1);
    hdst[i] = H; ldst[i] = L;
}

// W_mod[m][k][n] -> transposed hi/lo planes [m][n][k]
__global__ void __launch_bounds__(256) wconv(const float* __restrict__ W,
                                             __nv_bfloat16* __restrict__ wh,
                                             __nv_bfloat16* __restrict__ wl) {
    __shared__ float t[32][33];
    int m = blockIdx.z, n0 = blockIdx.x * 32, k0 = blockIdx.y * 32;
    int tx = threadIdx.x, ty = threadIdx.y;   // 32 x 8
    const float* Wm = W + (size_t)m * Hn * Hn;
#pragma unroll
    for (int j = 0; j < 4; j++)
        t[ty + 8 * j][tx] = Wm[(size_t)(k0 + ty + 8 * j) * Hn + n0 + tx];
    __syncthreads();
#pragma unroll
    for (int j = 0; j < 4; j++) {
        int n = ty + 8 * j;
        float v = t[tx][n];
        __nv_bfloat16 hv, lv;
        bsplit(v, hv, lv);
        size_t o = ((size_t)m * Hn + n0 + n) * Hn + k0 + tx;
        wh[o] = hv; wl[o] = lv;
    }
}

// ======================= legacy fp32-input GEMM path (small GEMMs) ==========
__device__ __forceinline__ void loadAf(__nv_bfloat16 (*sAh)[40], __nv_bfloat16 (*sAl)[40],
                                       const float* __restrict__ A, int lda, int tid) {
    int r0 = tid >> 3, kc = (tid & 7) << 2;
#pragma unroll
    for (int p = 0; p < 4; p++) {
        int r = p * 32 + r0;
        float4 v = *reinterpret_cast<const float4*>(A + (size_t)r * lda + kc);
        __nv_bfloat16 h0,h1,h2,h3,l0,l1,l2,l3;
        bsplit(v.x,h0,l0); bsplit(v.y,h1,l1); bsplit(v.z,h2,l2); bsplit(v.w,h3,l3);
        *reinterpret_cast<__nv_bfloat162*>(&sAh[r][kc])   = __halves2bfloat162(h0,h1);
        *reinterpret_cast<__nv_bfloat162*>(&sAh[r][kc+2]) = __halves2bfloat162(h2,h3);
        *reinterpret_cast<__nv_bfloat162*>(&sAl[r][kc])   = __halves2bfloat162(l0,l1);
        *reinterpret_cast<__nv_bfloat162*>(&sAl[r][kc+2]) = __halves2bfloat162(l2,l3);
    }
}
__device__ __forceinline__ void loadBf(__nv_bfloat16 (*sBh)[40], __nv_bfloat16 (*sBl)[40],
                                       const float* __restrict__ Wt, int ldb, int tid) {
    int n = tid & 127, kb = (tid >> 7) << 2;
#pragma unroll
    for (int p = 0; p < 4; p++) {
        int k = p * 8 + kb;
        float x0 = Wt[(size_t)(k+0)*ldb+n], x1 = Wt[(size_t)(k+1)*ldb+n];
        float x2 = Wt[(size_t)(k+2)*ldb+n], x3 = Wt[(size_t)(k+3)*ldb+n];
        __nv_bfloat16 h0,h1,h2,h3,l0,l1,l2,l3;
        bsplit(x0,h0,l0); bsplit(x1,h1,l1); bsplit(x2,h2,l2); bsplit(x3,h3,l3);
        *reinterpret_cast<__nv_bfloat162*>(&sBh[n][k])   = __halves2bfloat162(h0,h1);
        *reinterpret_cast<__nv_bfloat162*>(&sBh[n][k+2]) = __halves2bfloat162(h2,h3);
        *reinterpret_cast<__nv_bfloat162*>(&sBl[n][k])   = __halves2bfloat162(l0,l1);
        *reinterpret_cast<__nv_bfloat162*>(&sBl[n][k+2]) = __halves2bfloat162(l2,l3);
    }
}
__device__ __forceinline__ void mma_stepf(float c[4][4][4],
                                          __nv_bfloat16 (*sAh)[40], __nv_bfloat16 (*sAl)[40],
                                          __nv_bfloat16 (*sBh)[40], __nv_bfloat16 (*sBl)[40],
                                          int kk, int wm, int wn, int lane) {
    int qr = lane >> 2, qc2 = (lane & 3) << 1;
    uint32_t ah[4][4], al[4][4];
#pragma unroll
    for (int im = 0; im < 4; im++) {
        int rb = wm + im * 16 + qr;
        ah[im][0] = *reinterpret_cast<const uint32_t*>(&sAh[rb][kk+qc2]);
        ah[im][1] = *reinterpret_cast<const uint32_t*>(&sAh[rb+8][kk+qc2]);
        ah[im][2] = *reinterpret_cast<const uint32_t*>(&sAh[rb][kk+qc2+8]);
        ah[im][3] = *reinterpret_cast<const uint32_t*>(&sAh[rb+8][kk+qc2+8]);
        al[im][0] = *reinterpret_cast<const uint32_t*>(&sAl[rb][kk+qc2]);
        al[im][1] = *reinterpret_cast<const uint32_t*>(&sAl[rb+8][kk+qc2]);
        al[im][2] = *reinterpret_cast<const uint32_t*>(&sAl[rb][kk+qc2+8]);
        al[im][3] = *reinterpret_cast<const uint32_t*>(&sAl[rb+8][kk+qc2+8]);
    }
#pragma unroll
    for (int in = 0; in < 4; in++) {
        int cb = wn + in * 8 + qr;
        uint32_t bh[2], bl[2];
        bh[0] = *reinterpret_cast<const uint32_t*>(&sBh[cb][kk+qc2]);
        bh[1] = *reinterpret_cast<const uint32_t*>(&sBh[cb][kk+qc2+8]);
        bl[0] = *reinterpret_cast<const uint32_t*>(&sBl[cb][kk+qc2]);
        bl[1] = *reinterpret_cast<const uint32_t*>(&sBl[cb][kk+qc2+8]);
#pragma unroll
        for (int im = 0; im < 4; im++) {
            mma_bf16(c[im][in], ah[im], bh);
            mma_bf16(c[im][in], ah[im], bl);
            mma_bf16(c[im][in], al[im], bh);
        }
    }
}
template <int MODE>
__global__ void __launch_bounds__(256) gemm_kernel(
    const float* __restrict__ A, int lda, const float* __restrict__ W, int ldb,
    const float* __restrict__ bias, float* __restrict__ C, int N, int K) {
    __shared__ __nv_bfloat16 sAh[128][40], sAl[128][40], sBh[128][40], sBl[128][40];
    int tid = threadIdx.x, lane = tid & 31, wid = tid >> 5;
    int wm = (wid & 1) * 64, wn = (wid >> 1) * 32;
    int bR = blockIdx.y * 128, bC = blockIdx.x * 128;
    float c[4][4][4];
#pragma unroll
    for (int i = 0; i < 4; i++)
#pragma unroll
        for (int j = 0; j < 4; j++)
#pragma unroll
            for (int q = 0; q < 4; q++) c[i][j][q] = 0.f;
    const float* Ap = A + (size_t)bR * lda;
    const float* Wp = W + bC;
    for (int kt = 0; kt < K; kt += 32) {
        loadAf(sAh, sAl, Ap + kt, lda, tid);
        loadBf(sBh, sBl, Wp + (size_t)kt * ldb, ldb, tid);
        __syncthreads();
        mma_stepf(c, sAh, sAl, sBh, sBl, 0,  wm, wn, lane);
        mma_stepf(c, sAh, sAl, sBh, sBl, 16, wm, wn, lane);
        __syncthreads();
    }
    int qr = lane >> 2, qc2 = (lane & 3) << 1;
#pragma unroll
    for (int im = 0; im < 4; im++) {
        int gr = bR + wm + im * 16 + qr;
#pragma unroll
        for (int in = 0; in < 4; in++) {
            int gc = bC + wn + in * 8 + qc2;
            float2 bv;
            if (MODE == 1) bv = *reinterpret_cast<const float2*>(&bias[gc & (Rn - 1)]);
            else           bv = *reinterpret_cast<const float2*>(&bias[gc]);
            float v0 = c[im][in][0] + bv.x, v1 = c[im][in][1] + bv.y;
            float v2 = c[im][in][2] + bv.x, v3 = c[im][in][3] + bv.y;
            if (MODE == 1) { v0=fmaxf(v0,0.f); v1=fmaxf(v1,0.f); v2=fmaxf(v2,0.f); v3=fmaxf(v3,0.f); }
            float2 r0 = {v0, v1}, r1 = {v2, v3};
            *reinterpret_cast<float2*>(&C[(size_t)gr * N + gc])       = r0;
            *reinterpret_cast<float2*>(&C[(size_t)(gr + 8) * N + gc]) = r1;
        }
    }
}

// ---------------- router prep + probs ---------------------------------------
__global__ void prep_wr1c(const float* __restrict__ Wr1, const float* __restrict__ Wc,
                          const float* __restrict__ bc, float* __restrict__ out) {
    int k = blockIdx.x, j = threadIdx.x;
    float w = Wr1[(size_t)k * Rn + j], wck = Wc[k], bck = bc[k];
#pragma unroll
    for (int c = 0; c < CYC; c++)
        out[(size_t)k * Hn + c * Rn + j] = ((float)c * wck + bck) * w;
}
__global__ void probs_kernel(const float* __restrict__ r, const float* __restrict__ Wr2,
                             const float* __restrict__ br2, float* __restrict__ probs) {
    int wid = threadIdx.x >> 5, lane = threadIdx.x & 31;
    int idx = blockIdx.x * 8 + wid;
    int b = idx >> 2, c = idx & 3;
    const float* rr = r + (size_t)b * Hn + c * Rn;
    float acc[8];
#pragma unroll
    for (int m = 0; m < 8; m++) acc[m] = 0.f;
    for (int k = lane; k < Rn; k += 32) {
        float rv = rr[k];
        float4 w0 = *reinterpret_cast<const float4*>(&Wr2[(size_t)k * 8]);
        float4 w1 = *reinterpret_cast<const float4*>(&Wr2[(size_t)k * 8 + 4]);
        acc[0]+=rv*w0.x; acc[1]+=rv*w0.y; acc[2]+=rv*w0.z; acc[3]+=rv*w0.w;
        acc[4]+=rv*w1.x; acc[5]+=rv*w1.y; acc[6]+=rv*w1.z; acc[7]+=rv*w1.w;
    }
#pragma unroll
    for (int off = 16; off > 0; off >>= 1)
#pragma unroll
        for (int m = 0; m < 8; m++) acc[m] += __shfl_xor_sync(0xffffffffu, acc[m], off);
    float mx = -1e30f;
#pragma unroll
    for (int m = 0; m < 8; m++) { acc[m] += br2[m]; mx = fmaxf(mx, acc[m]); }
    float s = 0.f;
#pragma unroll
    for (int m = 0; m < 8; m++) { acc[m] = expf(acc[m] - mx); s += acc[m]; }
    float inv = 1.f / s;
    if (lane < 8) probs[(size_t)idx * 8 + lane] = acc[lane] * inv;
}

// ---------------- launch -----------------------------------------------------
extern "C" void kernel_launch(void* const* d_in, const int* in_sizes, int n_in,
                              void* d_out, int out_size) {
    (void)in_sizes; (void)n_in; (void)out_size;
    const float* x     = (const float*)d_in[0];
    const float* W_in  = (const float*)d_in[1];
    const float* b_in  = (const float*)d_in[2];
    const float* W_mod = (const float*)d_in[3];
    const float* b_mod = (const float*)d_in[4];
    const float* Wr1   = (const float*)d_in[5];
    const float* br1   = (const float*)d_in[6];
    const float* Wr2   = (const float*)d_in[7];
    const float* br2   = (const float*)d_in[8];
    const float* Wc    = (const float*)d_in[9];
    const float* bc    = (const float*)d_in[10];
    const float* W_out = (const float*)d_in[11];
    const float* b_out = (const float*)d_in[12];
    float* out = (float*)d_out;

    float *h, *r, *probs, *wr1c;
    __nv_bfloat16 *ahA, *alA, *ahB, *alB, *wh, *wl;
    cudaGetSymbolAddress((void**)&h,     g_h);
    cudaGetSymbolAddress((void**)&r,     g_r);
    cudaGetSymbolAddress((void**)&probs, g_probs);
    cudaGetSymbolAddress((void**)&wr1c,  g_wr1c);
    cudaGetSymbolAddress((void**)&ahA,   g_ahA);
    cudaGetSymbolAddress((void**)&alA,   g_alA);
    cudaGetSymbolAddress((void**)&ahB,   g_ahB);
    cudaGetSymbolAddress((void**)&alB,   g_alB);
    cudaGetSymbolAddress((void**)&wh,    g_wh);
    cudaGetSymbolAddress((void**)&wl,    g_wl);

    cudaFuncSetAttribute(expert_pl, cudaFuncAttributeMaxDynamicSharedMemorySize, SMEM_TOT);

    dim3 blk(256);
    dim3 eblk(ETHR);
    dim3 gH(Hn / 128, Bn / 128);
    dim3 gO(OUTn / 128, Bn / 128);
    dim3 gW(Hn / 32, Hn / 32, Mn);
    dim3 gE(Hn / 128, Bn / 128);

    // 0. one-time operand prep
    prep_wr1c<<<Hn, 256>>>(Wr1, Wc, bc, wr1c);
    wconv<<<gW, dim3(32, 8)>>>(W_mod, wh, wl);
    // 1. h = x @ W_in + b_in (also "orig")
    gemm_kernel<0><<<gH, blk>>>(x, INn, W_in, Hn, b_in, h, Hn, INn);
    // 2. router features (all cycles folded) + probs
    gemm_kernel<1><<<gH, blk>>>(h, Hn, wr1c, Hn, br1, r, Hn, Hn);
    probs_kernel<<<(Bn * CYC) / 8, 256>>>(r, Wr2, br2, probs);
    // 3. split h into bf16 planes once; experts ping-pong planes themselves
    hconv<<<(Bn * Hn) / (256 * 4), 256>>>((const float4*)h, (uint2*)ahA, (uint2*)alA);
    expert_pl<<<gE, eblk, SMEM_TOT>>>(ahA, alA, wh, wl, ahB, alB, h, 0, b_mod, probs, 0);
    expert_pl<<<gE, eblk, SMEM_TOT>>>(ahB, alB, wh, wl, ahA, alA, h, 0, b_mod, probs, 1);
    expert_pl<<<gE, eblk, SMEM_TOT>>>(ahA, alA, wh, wl, ahB, alB, h, 0, b_mod, probs, 2);
    expert_pl<<<gE, eblk, SMEM_TOT>>>(ahB, alB, wh, wl, ahA, alA, h, 1, b_mod, probs, 3);
    // 4. out = h @ W_out + b_out
    gemm_kernel<0><<<gO, blk>>>(h, Hn, W_out, OUTn, b_out, out, OUTn, Hn);
}

// round 13
// speedup vs baseline: 1.0017x; 1.0017x over previous
#include <cuda_runtime.h>
#include <cuda_bf16.h>
#include <cstdint>

#define Bn   16384
#define INn  512
#define Hn   1024
#define OUTn 512
#define Mn   8
#define Rn   256
#define CYC  4

// ---------------- scratch (static device globals; no runtime allocation) ----
__device__ float g_h   [(size_t)Bn * Hn];            // 64 MB
__device__ float g_r   [(size_t)Bn * Hn];            // 64 MB router features
__device__ float g_probs[(size_t)Bn * CYC * Mn];     // 2 MB
__device__ float g_wr1c[(size_t)Hn * Hn];            // 4 MB
__device__ __nv_bfloat16 g_ahA[(size_t)Bn * Hn];     // 32 MB  A hi plane (row-major [b][k])
__device__ __nv_bfloat16 g_alA[(size_t)Bn * Hn];     // 32 MB  A lo plane
__device__ __nv_bfloat16 g_ahB[(size_t)Bn * Hn];     // 32 MB  ping-pong
__device__ __nv_bfloat16 g_alB[(size_t)Bn * Hn];     // 32 MB
__device__ __nv_bfloat16 g_wh[(size_t)Mn * Hn * Hn]; // 16 MB W_mod^T hi [m][n][k]
__device__ __nv_bfloat16 g_wl[(size_t)Mn * Hn * Hn]; // 16 MB W_mod^T lo

// ---------------- helpers ---------------------------------------------------
__device__ __forceinline__ void bsplit(float x, __nv_bfloat16& h, __nv_bfloat16& l) {
    h = __float2bfloat16(x);
    l = __float2bfloat16(x - __bfloat162float(h));
}

__device__ __forceinline__ void mma_bf16(float* c, const uint32_t* a, const uint32_t* b) {
    asm volatile(
        "mma.sync.aligned.m16n8k16.row.col.f32.bf16.bf16.f32 "
        "{%0,%1,%2,%3}, {%4,%5,%6,%7}, {%8,%9}, {%0,%1,%2,%3};\n"
        : "+f"(c[0]), "+f"(c[1]), "+f"(c[2]), "+f"(c[3])
        : "r"(a[0]), "r"(a[1]), "r"(a[2]), "r"(a[3]), "r"(b[0]), "r"(b[1]));
}

__device__ __forceinline__ void ldsm4(uint32_t* r, uint32_t a) {
    asm volatile("ldmatrix.sync.aligned.m8n8.x4.shared.b16 {%0,%1,%2,%3}, [%4];\n"
        : "=r"(r[0]), "=r"(r[1]), "=r"(r[2]), "=r"(r[3]) : "r"(a));
}

__device__ __forceinline__ void cp16(uint32_t dst, const void* src) {
    asm volatile("cp.async.cg.shared.global [%0], [%1], 16;\n" :: "r"(dst), "l"(src));
}
#define CP_COMMIT() asm volatile("cp.async.commit_group;\n" ::: "memory")
#define CP_WAIT1()  asm volatile("cp.async.wait_group 1;\n" ::: "memory")
#define CP_WAIT0()  asm volatile("cp.async.wait_group 0;\n" ::: "memory")

// split 8 floats into packed bf16 hi/lo 16B vectors
__device__ __forceinline__ void split8(const float* v, uint4& H, uint4& L) {
    uint32_t h[4], l[4];
#pragma unroll
    for (int q = 0; q < 4; q++) {
        __nv_bfloat16 h0 = __float2bfloat16(v[2*q]);
        __nv_bfloat16 h1 = __float2bfloat16(v[2*q+1]);
        __nv_bfloat16 l0 = __float2bfloat16(v[2*q]   - __bfloat162float(h0));
        __nv_bfloat16 l1 = __float2bfloat16(v[2*q+1] - __bfloat162float(h1));
        __nv_bfloat162 hh = __halves2bfloat162(h0, h1);
        __nv_bfloat162 ll = __halves2bfloat162(l0, l1);
        h[q] = *reinterpret_cast<uint32_t*>(&hh);
        l[q] = *reinterpret_cast<uint32_t*>(&ll);
    }
    H = make_uint4(h[0], h[1], h[2], h[3]);
    L = make_uint4(l[0], l[1], l[2], l[3]);
}

// ======================= pipelined expert kernel (16 warps) =================
#define PLANE   5120                 // 128 rows * 40 elems per plane
#define STAGEE  (4 * PLANE)          // elems per stage (Ah,Al,Bh,Bl)
#define STAGEB  (STAGEE * 2)         // 40960 bytes
#define OSM_OFF (3 * STAGEB)         // 122880
#define OSM_STR 132                  // fp32 stride (multiple of 4)
#define SMEM_TOT (OSM_OFF + 128 * OSM_STR * 4)   // 122880 + 67584 = 190464
#define NIT     (Mn * 32)            // 256 iterations: 8 experts x 32 ktiles
#define ETHR    512                  // expert kernel threads (16 warps)

// copy one 128x32 ktile of A(hi/lo) + B(hi/lo) planes into a smem stage (512 thr)
__device__ __forceinline__ void stage_load(
    __nv_bfloat16* smstage,
    const __nv_bfloat16* __restrict__ Ah, const __nv_bfloat16* __restrict__ Al,
    const __nv_bfloat16* __restrict__ Bh, const __nv_bfloat16* __restrict__ Bl,
    int tid) {
    int row = tid >> 2;            // 0..127
    int c   = (tid & 3) * 8;       // 0,8,16,24
    uint32_t base = (uint32_t)__cvta_generic_to_shared(smstage);
    uint32_t d = base + (uint32_t)(row * 40 + c) * 2;
    size_t go = (size_t)row * Hn + c;
    cp16(d,                  Ah + go);
    cp16(d + PLANE * 2,      Al + go);
    cp16(d + 2 * PLANE * 2,  Bh + go);
    cp16(d + 3 * PLANE * 2,  Bl + go);
}

// one 32-k tile of bf16x3 mma (AhBh + AhBl + AlBh), 32x32 warp tile
__device__ __forceinline__ void ktile_mma(const __nv_bfloat16* smstage,
                                          float c[2][4][4], int wm, int wn, int lane) {
    uint32_t base = (uint32_t)__cvta_generic_to_shared(smstage);
    int r  = lane & 15;
    int cb = (lane >> 4) * 8;
#pragma unroll
    for (int kk = 0; kk < 32; kk += 16) {
        uint32_t ah[2][4], al[2][4], bh[4][2], bl[4][2];
#pragma unroll
        for (int im = 0; im < 2; im++) {
            uint32_t a = base + (uint32_t)((wm + im * 16 + r) * 40 + kk + cb) * 2;
            ldsm4(ah[im], a);
            ldsm4(al[im], a + PLANE * 2);
        }
#pragma unroll
        for (int p = 0; p < 2; p++) {
            uint32_t b = base + (uint32_t)(2 * PLANE + (wn + p * 16 + r) * 40 + kk + cb) * 2;
            uint32_t t[4];
            ldsm4(t, b);
            bh[2 * p][0] = t[0]; bh[2 * p][1] = t[2];
            bh[2 * p + 1][0] = t[1]; bh[2 * p + 1][1] = t[3];
            ldsm4(t, b + PLANE * 2);
            bl[2 * p][0] = t[0]; bl[2 * p][1] = t[2];
            bl[2 * p + 1][0] = t[1]; bl[2 * p + 1][1] = t[3];
        }
#pragma unroll
        for (int in = 0; in < 4; in++)
#pragma unroll
            for (int im = 0; im < 2; im++) {
                mma_bf16(c[im][in], ah[im], bh[in]);
                mma_bf16(c[im][in], ah[im], bl[in]);
                mma_bf16(c[im][in], al[im], bh[in]);
            }
    }
}

// dst = sum_m probs[.,cyc,m] * relu(src @ W_mod[m] + b_mod[m]); emits next-cycle
// bf16 hi/lo planes, and fp32 h when wf32 != 0. Mixture accumulator in smem.
__global__ void __launch_bounds__(ETHR, 1) expert_pl(
    const __nv_bfloat16* __restrict__ Ah, const __nv_bfloat16* __restrict__ Al,
    const __nv_bfloat16* __restrict__ Wh, const __nv_bfloat16* __restrict__ Wl,
    __nv_bfloat16* __restrict__ Oh, __nv_bfloat16* __restrict__ Ol,
    float* __restrict__ dstf, int wf32,
    const float* __restrict__ bmod, const float* __restrict__ probs, int cyc) {
    extern __shared__ char smem[];
    __nv_bfloat16* stg = reinterpret_cast<__nv_bfloat16*>(smem);
    float* o_f = reinterpret_cast<float*>(smem + OSM_OFF);
    int tid = threadIdx.x, lane = tid & 31, wid = tid >> 5;
    int wm = (wid & 3) * 32, wn = (wid >> 2) * 32;   // 4x4 warp grid, 32x32 tiles
    int bR = blockIdx.y * 128, bC = blockIdx.x * 128;
    int qr = lane >> 2, qc2 = (lane & 3) << 1;

    for (int i = tid; i < 128 * OSM_STR; i += ETHR) o_f[i] = 0.f;

    const __nv_bfloat16* Ab_h = Ah + (size_t)bR * Hn;
    const __nv_bfloat16* Ab_l = Al + (size_t)bR * Hn;
    const __nv_bfloat16* Bb_h = Wh + (size_t)bC * Hn;
    const __nv_bfloat16* Bb_l = Wl + (size_t)bC * Hn;

    // stage s: expert m = s>>5, ktile t = s&31
    auto ld_stage = [&](int s) {
        int m = s >> 5, t = s & 31;
        size_t boff = (size_t)m * Hn * Hn + (size_t)t * 32;
        stage_load(stg + (s % 3) * STAGEE,
                   Ab_h + t * 32, Ab_l + t * 32,
                   Bb_h + boff, Bb_l + boff, tid);
    };
    ld_stage(0); CP_COMMIT();
    ld_stage(1); CP_COMMIT();

    float c[2][4][4];
#pragma unroll
    for (int i = 0; i < 2; i++)
#pragma unroll
        for (int j = 0; j < 4; j++)
#pragma unroll
            for (int q = 0; q < 4; q++) c[i][j][q] = 0.f;

    for (int it = 0; it < NIT; it++) {
        if (it < NIT - 1) CP_WAIT1(); else CP_WAIT0();
        __syncthreads();
        int nxt = it + 2;
        if (nxt < NIT) { ld_stage(nxt); CP_COMMIT(); }

        ktile_mma(stg + (it % 3) * STAGEE, c, wm, wn, lane);

        if ((it & 31) == 31) {            // end of expert m: fold into smem o
            int m = it >> 5;
#pragma unroll
            for (int im = 0; im < 2; im++) {
                int r0 = wm + im * 16 + qr;
                int gr = bR + r0;
                float p0 = probs[((size_t)gr * CYC + cyc) * Mn + m];
                float p8 = probs[((size_t)(gr + 8) * CYC + cyc) * Mn + m];
#pragma unroll
                for (int in = 0; in < 4; in++) {
                    int col = wn + in * 8 + qc2;
                    float2 bv = *reinterpret_cast<const float2*>(&bmod[(size_t)m * Hn + bC + col]);
                    float2* s0 = reinterpret_cast<float2*>(&o_f[r0 * OSM_STR + col]);
                    float2* s8 = reinterpret_cast<float2*>(&o_f[(r0 + 8) * OSM_STR + col]);
                    float2 v0 = *s0, v8 = *s8;
                    v0.x += p0 * fmaxf(c[im][in][0] + bv.x, 0.f);
                    v0.y += p0 * fmaxf(c[im][in][1] + bv.y, 0.f);
                    v8.x += p8 * fmaxf(c[im][in][2] + bv.x, 0.f);
                    v8.y += p8 * fmaxf(c[im][in][3] + bv.y, 0.f);
                    *s0 = v0; *s8 = v8;
                    c[im][in][0] = 0.f; c[im][in][1] = 0.f;
                    c[im][in][2] = 0.f; c[im][in][3] = 0.f;
                }
            }
        }
    }
    __syncthreads();

    // coalesced epilogue: write next-cycle planes (+ fp32 h on last cycle)
    int row = tid >> 2, cs = (tid & 3) * 32;
    int gr = bR + row;
    size_t goff = (size_t)gr * Hn + bC + cs;
#pragma unroll
    for (int u = 0; u < 4; u++) {
        float4 a0 = *reinterpret_cast<float4*>(&o_f[row * OSM_STR + cs + u * 8]);
        float4 a1 = *reinterpret_cast<float4*>(&o_f[row * OSM_STR + cs + u * 8 + 4]);
        float v[8] = {a0.x, a0.y, a0.z, a0.w, a1.x, a1.y, a1.z, a1.w};
        uint4 H, L;
        split8(v, H, L);
        *reinterpret_cast<uint4*>(Oh + goff + u * 8) = H;
        *reinterpret_cast<uint4*>(Ol + goff + u * 8) = L;
        if (wf32) {
            *reinterpret_cast<float4*>(dstf + goff + u * 8)     = a0;
            *reinterpret_cast<float4*>(dstf + goff + u * 8 + 4) = a1;
        }
    }
}

// ======================= conversion kernels =================================
// h (fp32) -> hi/lo bf16 planes, row-major [b][k]
__global__ void __launch_bounds__(256) hconv(const float4* __restrict__ src,
                                             uint2* __restrict__ hdst,
                                             uint2* __restrict__ ldst) {
    size_t i = (size_t)blockIdx.x * 256 + threadIdx.x;
    float4 v = src[i];
    __nv_bfloat16 h0, h1, h2, h3, l0, l1, l2, l3;
    bsplit(v.x, h0, l0); bsplit(v.y, h1, l1);
    bsplit(v.z, h2, l2); bsplit(v.w, h3, l3);
    __nv_bfloat162 H0 = __halves2bfloat162(h0, h1), H1 = __halves2bfloat162(h2, h3);
    __nv_bfloat162 L0 = __halves2bfloat162(l0, l1), L1 = __halves2bfloat162(l2, l3);
    uint2 H, L;
    H.x = *reinterpret_cast<uint32_t*>(&H0); H.y = *reinterpret_cast<uint32_t*>(&H1);
    L.x = *reinterpret_cast<uint32_t*>(&L0); L.y = *reinterpret_cast<uint32_t*>(&L1);
    hdst[i] = H; ldst[i] = L;
}

// W_mod[m][k][n] -> transposed hi/lo planes [m][n][k]
__global__ void __launch_bounds__(256) wconv(const float* __restrict__ W,
                                             __nv_bfloat16* __restrict__ wh,
                                             __nv_bfloat16* __restrict__ wl) {
    __shared__ float t[32][33];
    int m = blockIdx.z, n0 = blockIdx.x * 32, k0 = blockIdx.y * 32;
    int tx = threadIdx.x, ty = threadIdx.y;   // 32 x 8
    const float* Wm = W + (size_t)m * Hn * Hn;
#pragma unroll
    for (int j = 0; j < 4; j++)
        t[ty + 8 * j][tx] = Wm[(size_t)(k0 + ty + 8 * j) * Hn + n0 + tx];
    __syncthreads();
#pragma unroll
    for (int j = 0; j < 4; j++) {
        int n = ty + 8 * j;
        float v = t[tx][n];
        __nv_bfloat16 hv, lv;
        bsplit(v, hv, lv);
        size_t o = ((size_t)m * Hn + n0 + n) * Hn + k0 + tx;
        wh[o] = hv; wl[o] = lv;
    }
}

// ======================= legacy fp32-input GEMM path (small GEMMs) ==========
__device__ __forceinline__ void loadAf(__nv_bfloat16 (*sAh)[40], __nv_bfloat16 (*sAl)[40],
                                       const float* __restrict__ A, int lda, int tid) {
    int r0 = tid >> 3, kc = (tid & 7) << 2;
#pragma unroll
    for (int p = 0; p < 4; p++) {
        int r = p * 32 + r0;
        float4 v = *reinterpret_cast<const float4*>(A + (size_t)r * lda + kc);
        __nv_bfloat16 h0,h1,h2,h3,l0,l1,l2,l3;
        bsplit(v.x,h0,l0); bsplit(v.y,h1,l1); bsplit(v.z,h2,l2); bsplit(v.w,h3,l3);
        *reinterpret_cast<__nv_bfloat162*>(&sAh[r][kc])   = __halves2bfloat162(h0,h1);
        *reinterpret_cast<__nv_bfloat162*>(&sAh[r][kc+2]) = __halves2bfloat162(h2,h3);
        *reinterpret_cast<__nv_bfloat162*>(&sAl[r][kc])   = __halves2bfloat162(l0,l1);
        *reinterpret_cast<__nv_bfloat162*>(&sAl[r][kc+2]) = __halves2bfloat162(l2,l3);
    }
}
__device__ __forceinline__ void loadBf(__nv_bfloat16 (*sBh)[40], __nv_bfloat16 (*sBl)[40],
                                       const float* __restrict__ Wt, int ldb, int tid) {
    int n = tid & 127, kb = (tid >> 7) << 2;
#pragma unroll
    for (int p = 0; p < 4; p++) {
        int k = p * 8 + kb;
        float x0 = Wt[(size_t)(k+0)*ldb+n], x1 = Wt[(size_t)(k+1)*ldb+n];
        float x2 = Wt[(size_t)(k+2)*ldb+n], x3 = Wt[(size_t)(k+3)*ldb+n];
        __nv_bfloat16 h0,h1,h2,h3,l0,l1,l2,l3;
        bsplit(x0,h0,l0); bsplit(x1,h1,l1); bsplit(x2,h2,l2); bsplit(x3,h3,l3);
        *reinterpret_cast<__nv_bfloat162*>(&sBh[n][k])   = __halves2bfloat162(h0,h1);
        *reinterpret_cast<__nv_bfloat162*>(&sBh[n][k+2]) = __halves2bfloat162(h2,h3);
        *reinterpret_cast<__nv_bfloat162*>(&sBl[n][k])   = __halves2bfloat162(l0,l1);
        *reinterpret_cast<__nv_bfloat162*>(&sBl[n][k+2]) = __halves2bfloat162(l2,l3);
    }
}
__device__ __forceinline__ void mma_stepf(float c[4][4][4],
                                          __nv_bfloat16 (*sAh)[40], __nv_bfloat16 (*sAl)[40],
                                          __nv_bfloat16 (*sBh)[40], __nv_bfloat16 (*sBl)[40],
                                          int kk, int wm, int wn, int lane) {
    int qr = lane >> 2, qc2 = (lane & 3) << 1;
    uint32_t ah[4][4], al[4][4];
#pragma unroll
    for (int im = 0; im < 4; im++) {
        int rb = wm + im * 16 + qr;
        ah[im][0] = *reinterpret_cast<const uint32_t*>(&sAh[rb][kk+qc2]);
        ah[im][1] = *reinterpret_cast<const uint32_t*>(&sAh[rb+8][kk+qc2]);
        ah[im][2] = *reinterpret_cast<const uint32_t*>(&sAh[rb][kk+qc2+8]);
        ah[im][3] = *reinterpret_cast<const uint32_t*>(&sAh[rb+8][kk+qc2+8]);
        al[im][0] = *reinterpret_cast<const uint32_t*>(&sAl[rb][kk+qc2]);
        al[im][1] = *reinterpret_cast<const uint32_t*>(&sAl[rb+8][kk+qc2]);
        al[im][2] = *reinterpret_cast<const uint32_t*>(&sAl[rb][kk+qc2+8]);
        al[im][3] = *reinterpret_cast<const uint32_t*>(&sAl[rb+8][kk+qc2+8]);
    }
#pragma unroll
    for (int in = 0; in < 4; in++) {
        int cb = wn + in * 8 + qr;
        uint32_t bh[2], bl[2];
        bh[0] = *reinterpret_cast<const uint32_t*>(&sBh[cb][kk+qc2]);
        bh[1] = *reinterpret_cast<const uint32_t*>(&sBh[cb][kk+qc2+8]);
        bl[0] = *reinterpret_cast<const uint32_t*>(&sBl[cb][kk+qc2]);
        bl[1] = *reinterpret_cast<const uint32_t*>(&sBl[cb][kk+qc2+8]);
#pragma unroll
        for (int im = 0; im < 4; im++) {
            mma_bf16(c[im][in], ah[im], bh);
            mma_bf16(c[im][in], ah[im], bl);
            mma_bf16(c[im][in], al[im], bh);
        }
    }
}
template <int MODE>
__global__ void __launch_bounds__(256) gemm_kernel(
    const float* __restrict__ A, int lda, const float* __restrict__ W, int ldb,
    const float* __restrict__ bias, float* __restrict__ C, int N, int K) {
    __shared__ __nv_bfloat16 sAh[128][40], sAl[128][40], sBh[128][40], sBl[128][40];
    int tid = threadIdx.x, lane = tid & 31, wid = tid >> 5;
    int wm = (wid & 1) * 64, wn = (wid >> 1) * 32;
    int bR = blockIdx.y * 128, bC = blockIdx.x * 128;
    float c[4][4][4];
#pragma unroll
    for (int i = 0; i < 4; i++)
#pragma unroll
        for (int j = 0; j < 4; j++)
#pragma unroll
            for (int q = 0; q < 4; q++) c[i][j][q] = 0.f;
    const float* Ap = A + (size_t)bR * lda;
    const float* Wp = W + bC;
    for (int kt = 0; kt < K; kt += 32) {
        loadAf(sAh, sAl, Ap + kt, lda, tid);
        loadBf(sBh, sBl, Wp + (size_t)kt * ldb, ldb, tid);
        __syncthreads();
        mma_stepf(c, sAh, sAl, sBh, sBl, 0,  wm, wn, lane);
        mma_stepf(c, sAh, sAl, sBh, sBl, 16, wm, wn, lane);
        __syncthreads();
    }
    int qr = lane >> 2, qc2 = (lane & 3) << 1;
#pragma unroll
    for (int im = 0; im < 4; im++) {
        int gr = bR + wm + im * 16 + qr;
#pragma unroll
        for (int in = 0; in < 4; in++) {
            int gc = bC + wn + in * 8 + qc2;
            float2 bv;
            if (MODE == 1) bv = *reinterpret_cast<const float2*>(&bias[gc & (Rn - 1)]);
            else           bv = *reinterpret_cast<const float2*>(&bias[gc]);
            float v0 = c[im][in][0] + bv.x, v1 = c[im][in][1] + bv.y;
            float v2 = c[im][in][2] + bv.x, v3 = c[im][in][3] + bv.y;
            if (MODE == 1) { v0=fmaxf(v0,0.f); v1=fmaxf(v1,0.f); v2=fmaxf(v2,0.f); v3=fmaxf(v3,0.f); }
            float2 r0 = {v0, v1}, r1 = {v2, v3};
            *reinterpret_cast<float2*>(&C[(size_t)gr * N + gc])       = r0;
            *reinterpret_cast<float2*>(&C[(size_t)(gr + 8) * N + gc]) = r1;
        }
    }
}

// ---------------- router prep + probs ---------------------------------------
__global__ void prep_wr1c(const float* __restrict__ Wr1, const float* __restrict__ Wc,
                          const float* __restrict__ bc, float* __restrict__ out) {
    int k = blockIdx.x, j = threadIdx.x;
    float w = Wr1[(size_t)k * Rn + j], wck = Wc[k], bck = bc[k];
#pragma unroll
    for (int c = 0; c < CYC; c++)
        out[(size_t)k * Hn + c * Rn + j] = ((float)c * wck + bck) * w;
}
__global__ void probs_kernel(const float* __restrict__ r, const float* __restrict__ Wr2,
                             const float* __restrict__ br2, float* __restrict__ probs) {
    int wid = threadIdx.x >> 5, lane = threadIdx.x & 31;
    int idx = blockIdx.x * 8 + wid;
    int b = idx >> 2, c = idx & 3;
    const float* rr = r + (size_t)b * Hn + c * Rn;
    float acc[8];
#pragma unroll
    for (int m = 0; m < 8; m++) acc[m] = 0.f;
    for (int k = lane; k < Rn; k += 32) {
        float rv = rr[k];
        float4 w0 = *reinterpret_cast<const float4*>(&Wr2[(size_t)k * 8]);
        float4 w1 = *reinterpret_cast<const float4*>(&Wr2[(size_t)k * 8 + 4]);
        acc[0]+=rv*w0.x; acc[1]+=rv*w0.y; acc[2]+=rv*w0.z; acc[3]+=rv*w0.w;
        acc[4]+=rv*w1.x; acc[5]+=rv*w1.y; acc[6]+=rv*w1.z; acc[7]+=rv*w1.w;
    }
#pragma unroll
    for (int off = 16; off > 0; off >>= 1)
#pragma unroll
        for (int m = 0; m < 8; m++) acc[m] += __shfl_xor_sync(0xffffffffu, acc[m], off);
    float mx = -1e30f;
#pragma unroll
    for (int m = 0; m < 8; m++) { acc[m] += br2[m]; mx = fmaxf(mx, acc[m]); }
    float s = 0.f;
#pragma unroll
    for (int m = 0; m < 8; m++) { acc[m] = expf(acc[m] - mx); s += acc[m]; }
    float inv = 1.f / s;
    if (lane < 8) probs[(size_t)idx * 8 + lane] = acc[lane] * inv;
}

// ---------------- launch -----------------------------------------------------
extern "C" void kernel_launch(void* const* d_in, const int* in_sizes, int n_in,
                              void* d_out, int out_size) {
    (void)in_sizes; (void)n_in; (void)out_size;
    const float* x     = (const float*)d_in[0];
    const float* W_in  = (const float*)d_in[1];
    const float* b_in  = (const float*)d_in[2];
    const float* W_mod = (const float*)d_in[3];
    const float* b_mod = (const float*)d_in[4];
    const float* Wr1   = (const float*)d_in[5];
    const float* br1   = (const float*)d_in[6];
    const float* Wr2   = (const float*)d_in[7];
    const float* br2   = (const float*)d_in[8];
    const float* Wc    = (const float*)d_in[9];
    const float* bc    = (const float*)d_in[10];
    const float* W_out = (const float*)d_in[11];
    const float* b_out = (const float*)d_in[12];
    float* out = (float*)d_out;

    float *h, *r, *probs, *wr1c;
    __nv_bfloat16 *ahA, *alA, *ahB, *alB, *wh, *wl;
    cudaGetSymbolAddress((void**)&h,     g_h);
    cudaGetSymbolAddress((void**)&r,     g_r);
    cudaGetSymbolAddress((void**)&probs, g_probs);
    cudaGetSymbolAddress((void**)&wr1c,  g_wr1c);
    cudaGetSymbolAddress((void**)&ahA,   g_ahA);
    cudaGetSymbolAddress((void**)&alA,   g_alA);
    cudaGetSymbolAddress((void**)&ahB,   g_ahB);
    cudaGetSymbolAddress((void**)&alB,   g_alB);
    cudaGetSymbolAddress((void**)&wh,    g_wh);
    cudaGetSymbolAddress((void**)&wl,    g_wl);

    cudaFuncSetAttribute(expert_pl, cudaFuncAttributeMaxDynamicSharedMemorySize, SMEM_TOT);

    dim3 blk(256);
    dim3 eblk(ETHR);
    dim3 gH(Hn / 128, Bn / 128);
    dim3 gO(OUTn / 128, Bn / 128);
    dim3 gW(Hn / 32, Hn / 32, Mn);
    dim3 gE(Hn / 128, Bn / 128);

    // 0. one-time operand prep
    prep_wr1c<<<Hn, 256>>>(Wr1, Wc, bc, wr1c);
    wconv<<<gW, dim3(32, 8)>>>(W_mod, wh, wl);
    // 1. h = x @ W_in + b_in (also "orig")
    gemm_kernel<0><<<gH, blk>>>(x, INn, W_in, Hn, b_in, h, Hn, INn);
    // 2. router features (all cycles folded) + probs
    gemm_kernel<1><<<gH, blk>>>(h, Hn, wr1c, Hn, br1, r, Hn, Hn);
    probs_kernel<<<(Bn * CYC) / 8, 256>>>(r, Wr2, br2, probs);
    // 3. split h into bf16 planes once; experts ping-pong planes themselves
    hconv<<<(Bn * Hn) / (256 * 4), 256>>>((const float4*)h, (uint2*)ahA, (uint2*)alA);
    expert_pl<<<gE, eblk, SMEM_TOT>>>(ahA, alA, wh, wl, ahB, alB, h, 0, b_mod, probs, 0);
    expert_pl<<<gE, eblk, SMEM_TOT>>>(ahB, alB, wh, wl, ahA, alA, h, 0, b_mod, probs, 1);
    expert_pl<<<gE, eblk, SMEM_TOT>>>(ahA, alA, wh, wl, ahB, alB, h, 0, b_mod, probs, 2);
    expert_pl<<<gE, eblk, SMEM_TOT>>>(ahB, alB, wh, wl, ahA, alA, h, 1, b_mod, probs, 3);
    // 4. out = h @ W_out + b_out
    gemm_kernel<0><<<gO, blk>>>(h, Hn, W_out, OUTn, b_out, out, OUTn, Hn);
}

// round 14
// speedup vs baseline: 1.0020x; 1.0004x over previous
#include <cuda_runtime.h>
#include <cuda_bf16.h>
#include <cstdint>

#define Bn   16384
#define INn  512
#define Hn   1024
#define OUTn 512
#define Mn   8
#define Rn   256
#define CYC  4

// ---------------- scratch (static device globals; no runtime allocation) ----
__device__ float g_h   [(size_t)Bn * Hn];            // 64 MB
__device__ float g_r   [(size_t)Bn * Hn];            // 64 MB router features
__device__ float g_probs[(size_t)Bn * CYC * Mn];     // 2 MB
__device__ float g_wr1c[(size_t)Hn * Hn];            // 4 MB
__device__ __nv_bfloat16 g_ahA[(size_t)Bn * Hn];     // 32 MB  A hi plane (row-major [b][k])
__device__ __nv_bfloat16 g_alA[(size_t)Bn * Hn];     // 32 MB  A lo plane
__device__ __nv_bfloat16 g_ahB[(size_t)Bn * Hn];     // 32 MB  ping-pong
__device__ __nv_bfloat16 g_alB[(size_t)Bn * Hn];     // 32 MB
__device__ __nv_bfloat16 g_wh[(size_t)Mn * Hn * Hn]; // 16 MB W_mod^T hi [m][n][k]
__device__ __nv_bfloat16 g_wl[(size_t)Mn * Hn * Hn]; // 16 MB W_mod^T lo

// ---------------- helpers ---------------------------------------------------
__device__ __forceinline__ void bsplit(float x, __nv_bfloat16& h, __nv_bfloat16& l) {
    h = __float2bfloat16(x);
    l = __float2bfloat16(x - __bfloat162float(h));
}

__device__ __forceinline__ void mma_bf16(float* c, const uint32_t* a, const uint32_t* b) {
    asm volatile(
        "mma.sync.aligned.m16n8k16.row.col.f32.bf16.bf16.f32 "
        "{%0,%1,%2,%3}, {%4,%5,%6,%7}, {%8,%9}, {%0,%1,%2,%3};\n"
        : "+f"(c[0]), "+f"(c[1]), "+f"(c[2]), "+f"(c[3])
        : "r"(a[0]), "r"(a[1]), "r"(a[2]), "r"(a[3]), "r"(b[0]), "r"(b[1]));
}

__device__ __forceinline__ void ldsm4(uint32_t* r, uint32_t a) {
    asm volatile("ldmatrix.sync.aligned.m8n8.x4.shared.b16 {%0,%1,%2,%3}, [%4];\n"
        : "=r"(r[0]), "=r"(r[1]), "=r"(r[2]), "=r"(r[3]) : "r"(a));
}

__device__ __forceinline__ void cp16(uint32_t dst, const void* src) {
    asm volatile("cp.async.cg.shared.global [%0], [%1], 16;\n" :: "r"(dst), "l"(src));
}
#define CP_COMMIT() asm volatile("cp.async.commit_group;\n" ::: "memory")
#define CP_WAIT1()  asm volatile("cp.async.wait_group 1;\n" ::: "memory")
#define CP_WAIT0()  asm volatile("cp.async.wait_group 0;\n" ::: "memory")

// split 8 floats into packed bf16 hi/lo 16B vectors
__device__ __forceinline__ void split8(const float* v, uint4& H, uint4& L) {
    uint32_t h[4], l[4];
#pragma unroll
    for (int q = 0; q < 4; q++) {
        __nv_bfloat16 h0 = __float2bfloat16(v[2*q]);
        __nv_bfloat16 h1 = __float2bfloat16(v[2*q+1]);
        __nv_bfloat16 l0 = __float2bfloat16(v[2*q]   - __bfloat162float(h0));
        __nv_bfloat16 l1 = __float2bfloat16(v[2*q+1] - __bfloat162float(h1));
        __nv_bfloat162 hh = __halves2bfloat162(h0, h1);
        __nv_bfloat162 ll = __halves2bfloat162(l0, l1);
        h[q] = *reinterpret_cast<uint32_t*>(&hh);
        l[q] = *reinterpret_cast<uint32_t*>(&ll);
    }
    H = make_uint4(h[0], h[1], h[2], h[3]);
    L = make_uint4(l[0], l[1], l[2], l[3]);
}

// ======================= pipelined expert kernel (16 warps) =================
#define PLANE   5120                 // 128 rows * 40 elems per plane
#define STAGEE  (4 * PLANE)          // elems per stage (Ah,Al,Bh,Bl)
#define STAGEB  (STAGEE * 2)         // 40960 bytes
#define OSM_OFF (3 * STAGEB)         // 122880
#define OSM_STR 132                  // fp32 stride (multiple of 4)
#define SMEM_TOT (OSM_OFF + 128 * OSM_STR * 4)   // 122880 + 67584 = 190464
#define NIT     (Mn * 32)            // 256 iterations: 8 experts x 32 ktiles
#define ETHR    512                  // expert kernel threads (16 warps)

// copy one 128x32 ktile of A(hi/lo) + B(hi/lo) planes into a smem stage (512 thr)
__device__ __forceinline__ void stage_load(
    __nv_bfloat16* smstage,
    const __nv_bfloat16* __restrict__ Ah, const __nv_bfloat16* __restrict__ Al,
    const __nv_bfloat16* __restrict__ Bh, const __nv_bfloat16* __restrict__ Bl,
    int tid) {
    int row = tid >> 2;            // 0..127
    int c   = (tid & 3) * 8;       // 0,8,16,24
    uint32_t base = (uint32_t)__cvta_generic_to_shared(smstage);
    uint32_t d = base + (uint32_t)(row * 40 + c) * 2;
    size_t go = (size_t)row * Hn + c;
    cp16(d,                  Ah + go);
    cp16(d + PLANE * 2,      Al + go);
    cp16(d + 2 * PLANE * 2,  Bh + go);
    cp16(d + 3 * PLANE * 2,  Bl + go);
}

// one 32-k tile of bf16x3 mma (AhBh + AhBl + AlBh), 32x32 warp tile
__device__ __forceinline__ void ktile_mma(const __nv_bfloat16* smstage,
                                          float c[2][4][4], int wm, int wn, int lane) {
    uint32_t base = (uint32_t)__cvta_generic_to_shared(smstage);
    int r  = lane & 15;
    int cb = (lane >> 4) * 8;
#pragma unroll
    for (int kk = 0; kk < 32; kk += 16) {
        uint32_t ah[2][4], al[2][4], bh[4][2], bl[4][2];
#pragma unroll
        for (int im = 0; im < 2; im++) {
            uint32_t a = base + (uint32_t)((wm + im * 16 + r) * 40 + kk + cb) * 2;
            ldsm4(ah[im], a);
            ldsm4(al[im], a + PLANE * 2);
        }
#pragma unroll
        for (int p = 0; p < 2; p++) {
            uint32_t b = base + (uint32_t)(2 * PLANE + (wn + p * 16 + r) * 40 + kk + cb) * 2;
            uint32_t t[4];
            ldsm4(t, b);
            bh[2 * p][0] = t[0]; bh[2 * p][1] = t[2];
            bh[2 * p + 1][0] = t[1]; bh[2 * p + 1][1] = t[3];
            ldsm4(t, b + PLANE * 2);
            bl[2 * p][0] = t[0]; bl[2 * p][1] = t[2];
            bl[2 * p + 1][0] = t[1]; bl[2 * p + 1][1] = t[3];
        }
#pragma unroll
        for (int in = 0; in < 4; in++)
#pragma unroll
            for (int im = 0; im < 2; im++) {
                mma_bf16(c[im][in], ah[im], bh[in]);
                mma_bf16(c[im][in], ah[im], bl[in]);
                mma_bf16(c[im][in], al[im], bh[in]);
            }
    }
}

// dst = sum_m probs[.,cyc,m] * relu(src @ W_mod[m] + b_mod[m]); emits next-cycle
// bf16 hi/lo planes, and fp32 h when wf32 != 0. Mixture accumulator in smem.
__global__ void __launch_bounds__(ETHR, 1) expert_pl(
    const __nv_bfloat16* __restrict__ Ah, const __nv_bfloat16* __restrict__ Al,
    const __nv_bfloat16* __restrict__ Wh, const __nv_bfloat16* __restrict__ Wl,
    __nv_bfloat16* __restrict__ Oh, __nv_bfloat16* __restrict__ Ol,
    float* __restrict__ dstf, int wf32,
    const float* __restrict__ bmod, const float* __restrict__ probs, int cyc) {
    extern __shared__ char smem[];
    __nv_bfloat16* stg = reinterpret_cast<__nv_bfloat16*>(smem);
    float* o_f = reinterpret_cast<float*>(smem + OSM_OFF);
    int tid = threadIdx.x, lane = tid & 31, wid = tid >> 5;
    int wm = (wid & 3) * 32, wn = (wid >> 2) * 32;   // 4x4 warp grid, 32x32 tiles
    int bR = blockIdx.y * 128, bC = blockIdx.x * 128;
    int qr = lane >> 2, qc2 = (lane & 3) << 1;

    for (int i = tid; i < 128 * OSM_STR; i += ETHR) o_f[i] = 0.f;

    const __nv_bfloat16* Ab_h = Ah + (size_t)bR * Hn;
    const __nv_bfloat16* Ab_l = Al + (size_t)bR * Hn;
    const __nv_bfloat16* Bb_h = Wh + (size_t)bC * Hn;
    const __nv_bfloat16* Bb_l = Wl + (size_t)bC * Hn;

    // stage s: expert m = s>>5, ktile t = s&31
    auto ld_stage = [&](int s) {
        int m = s >> 5, t = s & 31;
        size_t boff = (size_t)m * Hn * Hn + (size_t)t * 32;
        stage_load(stg + (s % 3) * STAGEE,
                   Ab_h + t * 32, Ab_l + t * 32,
                   Bb_h + boff, Bb_l + boff, tid);
    };
    ld_stage(0); CP_COMMIT();
    ld_stage(1); CP_COMMIT();

    float c[2][4][4];
#pragma unroll
    for (int i = 0; i < 2; i++)
#pragma unroll
        for (int j = 0; j < 4; j++)
#pragma unroll
            for (int q = 0; q < 4; q++) c[i][j][q] = 0.f;

    for (int it = 0; it < NIT; it++) {
        if (it < NIT - 1) CP_WAIT1(); else CP_WAIT0();
        __syncthreads();
        int nxt = it + 2;
        if (nxt < NIT) { ld_stage(nxt); CP_COMMIT(); }

        ktile_mma(stg + (it % 3) * STAGEE, c, wm, wn, lane);

        if ((it & 31) == 31) {            // end of expert m: fold into smem o
            int m = it >> 5;
#pragma unroll
            for (int im = 0; im < 2; im++) {
                int r0 = wm + im * 16 + qr;
                int gr = bR + r0;
                float p0 = probs[((size_t)gr * CYC + cyc) * Mn + m];
                float p8 = probs[((size_t)(gr + 8) * CYC + cyc) * Mn + m];
#pragma unroll
                for (int in = 0; in < 4; in++) {
                    int col = wn + in * 8 + qc2;
                    float2 bv = *reinterpret_cast<const float2*>(&bmod[(size_t)m * Hn + bC + col]);
                    float2* s0 = reinterpret_cast<float2*>(&o_f[r0 * OSM_STR + col]);
                    float2* s8 = reinterpret_cast<float2*>(&o_f[(r0 + 8) * OSM_STR + col]);
                    float2 v0 = *s0, v8 = *s8;
                    v0.x += p0 * fmaxf(c[im][in][0] + bv.x, 0.f);
                    v0.y += p0 * fmaxf(c[im][in][1] + bv.y, 0.f);
                    v8.x += p8 * fmaxf(c[im][in][2] + bv.x, 0.f);
                    v8.y += p8 * fmaxf(c[im][in][3] + bv.y, 0.f);
                    *s0 = v0; *s8 = v8;
                    c[im][in][0] = 0.f; c[im][in][1] = 0.f;
                    c[im][in][2] = 0.f; c[im][in][3] = 0.f;
                }
            }
        }
    }
    __syncthreads();

    // coalesced epilogue: write next-cycle planes (+ fp32 h on last cycle)
    int row = tid >> 2, cs = (tid & 3) * 32;
    int gr = bR + row;
    size_t goff = (size_t)gr * Hn + bC + cs;
#pragma unroll
    for (int u = 0; u < 4; u++) {
        float4 a0 = *reinterpret_cast<float4*>(&o_f[row * OSM_STR + cs + u * 8]);
        float4 a1 = *reinterpret_cast<float4*>(&o_f[row * OSM_STR + cs + u * 8 + 4]);
        float v[8] = {a0.x, a0.y, a0.z, a0.w, a1.x, a1.y, a1.z, a1.w};
        uint4 H, L;
        split8(v, H, L);
        *reinterpret_cast<uint4*>(Oh + goff + u * 8) = H;
        *reinterpret_cast<uint4*>(Ol + goff + u * 8) = L;
        if (wf32) {
            *reinterpret_cast<float4*>(dstf + goff + u * 8)     = a0;
            *reinterpret_cast<float4*>(dstf + goff + u * 8 + 4) = a1;
        }
    }
}

// ======================= conversion kernels =================================
// h (fp32) -> hi/lo bf16 planes, row-major [b][k]
__global__ void __launch_bounds__(256) hconv(const float4* __restrict__ src,
                                             uint2* __restrict__ hdst,
                                             uint2* __restrict__ ldst) {
    size_t i = (size_t)blockIdx.x * 256 + threadIdx.x;
    float4 v = src[i];
    __nv_bfloat16 h0, h1, h2, h3, l0, l1, l2, l3;
    bsplit(v.x, h0, l0); bsplit(v.y, h1, l1);
    bsplit(v.z, h2, l2); bsplit(v.w, h3, l3);
    __nv_bfloat162 H0 = __halves2bfloat162(h0, h1), H1 = __halves2bfloat162(h2, h3);
    __nv_bfloat162 L0 = __halves2bfloat162(l0, l1), L1 = __halves2bfloat162(l2, l3);
    uint2 H, L;
    H.x = *reinterpret_cast<uint32_t*>(&H0); H.y = *reinterpret_cast<uint32_t*>(&H1);
    L.x = *reinterpret_cast<uint32_t*>(&L0); L.y = *reinterpret_cast<uint32_t*>(&L1);
    hdst[i] = H; ldst[i] = L;
}

// W_mod[m][k][n] -> transposed hi/lo planes [m][n][k]
__global__ void __launch_bounds__(256) wconv(const float* __restrict__ W,
                                             __nv_bfloat16* __restrict__ wh,
                                             __nv_bfloat16* __restrict__ wl) {
    __shared__ float t[32][33];
    int m = blockIdx.z, n0 = blockIdx.x * 32, k0 = blockIdx.y * 32;
    int tx = threadIdx.x, ty = threadIdx.y;   // 32 x 8
    const float* Wm = W + (size_t)m * Hn * Hn;
#pragma unroll
    for (int j = 0; j < 4; j++)
        t[ty + 8 * j][tx] = Wm[(size_t)(k0 + ty + 8 * j) * Hn + n0 + tx];
    __syncthreads();
#pragma unroll
    for (int j = 0; j < 4; j++) {
        int n = ty + 8 * j;
        float v = t[tx][n];
        __nv_bfloat16 hv, lv;
        bsplit(v, hv, lv);
        size_t o = ((size_t)m * Hn + n0 + n) * Hn + k0 + tx;
        wh[o] = hv; wl[o] = lv;
    }
}

// ======================= legacy fp32-input GEMM path (small GEMMs) ==========
__device__ __forceinline__ void loadAf(__nv_bfloat16 (*sAh)[40], __nv_bfloat16 (*sAl)[40],
                                       const float* __restrict__ A, int lda, int tid) {
    int r0 = tid >> 3, kc = (tid & 7) << 2;
#pragma unroll
    for (int p = 0; p < 4; p++) {
        int r = p * 32 + r0;
        float4 v = *reinterpret_cast<const float4*>(A + (size_t)r * lda + kc);
        __nv_bfloat16 h0,h1,h2,h3,l0,l1,l2,l3;
        bsplit(v.x,h0,l0); bsplit(v.y,h1,l1); bsplit(v.z,h2,l2); bsplit(v.w,h3,l3);
        *reinterpret_cast<__nv_bfloat162*>(&sAh[r][kc])   = __halves2bfloat162(h0,h1);
        *reinterpret_cast<__nv_bfloat162*>(&sAh[r][kc+2]) = __halves2bfloat162(h2,h3);
        *reinterpret_cast<__nv_bfloat162*>(&sAl[r][kc])   = __halves2bfloat162(l0,l1);
        *reinterpret_cast<__nv_bfloat162*>(&sAl[r][kc+2]) = __halves2bfloat162(l2,l3);
    }
}
__device__ __forceinline__ void loadBf(__nv_bfloat16 (*sBh)[40], __nv_bfloat16 (*sBl)[40],
                                       const float* __restrict__ Wt, int ldb, int tid) {
    int n = tid & 127, kb = (tid >> 7) << 2;
#pragma unroll
    for (int p = 0; p < 4; p++) {
        int k = p * 8 + kb;
        float x0 = Wt[(size_t)(k+0)*ldb+n], x1 = Wt[(size_t)(k+1)*ldb+n];
        float x2 = Wt[(size_t)(k+2)*ldb+n], x3 = Wt[(size_t)(k+3)*ldb+n];
        __nv_bfloat16 h0,h1,h2,h3,l0,l1,l2,l3;
        bsplit(x0,h0,l0); bsplit(x1,h1,l1); bsplit(x2,h2,l2); bsplit(x3,h3,l3);
        *reinterpret_cast<__nv_bfloat162*>(&sBh[n][k])   = __halves2bfloat162(h0,h1);
        *reinterpret_cast<__nv_bfloat162*>(&sBh[n][k+2]) = __halves2bfloat162(h2,h3);
        *reinterpret_cast<__nv_bfloat162*>(&sBl[n][k])   = __halves2bfloat162(l0,l1);
        *reinterpret_cast<__nv_bfloat162*>(&sBl[n][k+2]) = __halves2bfloat162(l2,l3);
    }
}
__device__ __forceinline__ void mma_stepf(float c[4][4][4],
                                          __nv_bfloat16 (*sAh)[40], __nv_bfloat16 (*sAl)[40],
                                          __nv_bfloat16 (*sBh)[40], __nv_bfloat16 (*sBl)[40],
                                          int kk, int wm, int wn, int lane) {
    int qr = lane >> 2, qc2 = (lane & 3) << 1;
    uint32_t ah[4][4], al[4][4];
#pragma unroll
    for (int im = 0; im < 4; im++) {
        int rb = wm + im * 16 + qr;
        ah[im][0] = *reinterpret_cast<const uint32_t*>(&sAh[rb][kk+qc2]);
        ah[im][1] = *reinterpret_cast<const uint32_t*>(&sAh[rb+8][kk+qc2]);
        ah[im][2] = *reinterpret_cast<const uint32_t*>(&sAh[rb][kk+qc2+8]);
        ah[im][3] = *reinterpret_cast<const uint32_t*>(&sAh[rb+8][kk+qc2+8]);
        al[im][0] = *reinterpret_cast<const uint32_t*>(&sAl[rb][kk+qc2]);
        al[im][1] = *reinterpret_cast<const uint32_t*>(&sAl[rb+8][kk+qc2]);
        al[im][2] = *reinterpret_cast<const uint32_t*>(&sAl[rb][kk+qc2+8]);
        al[im][3] = *reinterpret_cast<const uint32_t*>(&sAl[rb+8][kk+qc2+8]);
    }
#pragma unroll
    for (int in = 0; in < 4; in++) {
        int cb = wn + in * 8 + qr;
        uint32_t bh[2], bl[2];
        bh[0] = *reinterpret_cast<const uint32_t*>(&sBh[cb][kk+qc2]);
        bh[1] = *reinterpret_cast<const uint32_t*>(&sBh[cb][kk+qc2+8]);
        bl[0] = *reinterpret_cast<const uint32_t*>(&sBl[cb][kk+qc2]);
        bl[1] = *reinterpret_cast<const uint32_t*>(&sBl[cb][kk+qc2+8]);
#pragma unroll
        for (int im = 0; im < 4; im++) {
            mma_bf16(c[im][in], ah[im], bh);
            mma_bf16(c[im][in], ah[im], bl);
            mma_bf16(c[im][in], al[im], bh);
        }
    }
}
template <int MODE>
__global__ void __launch_bounds__(256) gemm_kernel(
    const float* __restrict__ A, int lda, const float* __restrict__ W, int ldb,
    const float* __restrict__ bias, float* __restrict__ C, int N, int K) {
    __shared__ __nv_bfloat16 sAh[128][40], sAl[128][40], sBh[128][40], sBl[128][40];
    int tid = threadIdx.x, lane = tid & 31, wid = tid >> 5;
    int wm = (wid & 1) * 64, wn = (wid >> 1) * 32;
    int bR = blockIdx.y * 128, bC = blockIdx.x * 128;
    float c[4][4][4];
#pragma unroll
    for (int i = 0; i < 4; i++)
#pragma unroll
        for (int j = 0; j < 4; j++)
#pragma unroll
            for (int q = 0; q < 4; q++) c[i][j][q] = 0.f;
    const float* Ap = A + (size_t)bR * lda;
    const float* Wp = W + bC;
    for (int kt = 0; kt < K; kt += 32) {
        loadAf(sAh, sAl, Ap + kt, lda, tid);
        loadBf(sBh, sBl, Wp + (size_t)kt * ldb, ldb, tid);
        __syncthreads();
        mma_stepf(c, sAh, sAl, sBh, sBl, 0,  wm, wn, lane);
        mma_stepf(c, sAh, sAl, sBh, sBl, 16, wm, wn, lane);
        __syncthreads();
    }
    int qr = lane >> 2, qc2 = (lane & 3) << 1;
#pragma unroll
    for (int im = 0; im < 4; im++) {
        int gr = bR + wm + im * 16 + qr;
#pragma unroll
        for (int in = 0; in < 4; in++) {
            int gc = bC + wn + in * 8 + qc2;
            float2 bv;
            if (MODE == 1) bv = *reinterpret_cast<const float2*>(&bias[gc & (Rn - 1)]);
            else           bv = *reinterpret_cast<const float2*>(&bias[gc]);
            float v0 = c[im][in][0] + bv.x, v1 = c[im][in][1] + bv.y;
            float v2 = c[im][in][2] + bv.x, v3 = c[im][in][3] + bv.y;
            if (MODE == 1) { v0=fmaxf(v0,0.f); v1=fmaxf(v1,0.f); v2=fmaxf(v2,0.f); v3=fmaxf(v3,0.f); }
            float2 r0 = {v0, v1}, r1 = {v2, v3};
            *reinterpret_cast<float2*>(&C[(size_t)gr * N + gc])       = r0;
            *reinterpret_cast<float2*>(&C[(size_t)(gr + 8) * N + gc]) = r1;
        }
    }
}

// ---------------- router prep + probs ---------------------------------------
__global__ void prep_wr1c(const float* __restrict__ Wr1, const float* __restrict__ Wc,
                          const float* __restrict__ bc, float* __restrict__ out) {
    int k = blockIdx.x, j = threadIdx.x;
    float w = Wr1[(size_t)k * Rn + j], wck = Wc[k], bck = bc[k];
#pragma unroll
    for (int c = 0; c < CYC; c++)
        out[(size_t)k * Hn + c * Rn + j] = ((float)c * wck + bck) * w;
}
__global__ void probs_kernel(const float* __restrict__ r, const float* __restrict__ Wr2,
                             const float* __restrict__ br2, float* __restrict__ probs) {
    int wid = threadIdx.x >> 5, lane = threadIdx.x & 31;
    int idx = blockIdx.x * 8 + wid;
    int b = idx >> 2, c = idx & 3;
    const float* rr = r + (size_t)b * Hn + c * Rn;
    float acc[8];
#pragma unroll
    for (int m = 0; m < 8; m++) acc[m] = 0.f;
    for (int k = lane; k < Rn; k += 32) {
        float rv = rr[k];
        float4 w0 = *reinterpret_cast<const float4*>(&Wr2[(size_t)k * 8]);
        float4 w1 = *reinterpret_cast<const float4*>(&Wr2[(size_t)k * 8 + 4]);
        acc[0]+=rv*w0.x; acc[1]+=rv*w0.y; acc[2]+=rv*w0.z; acc[3]+=rv*w0.w;
        acc[4]+=rv*w1.x; acc[5]+=rv*w1.y; acc[6]+=rv*w1.z; acc[7]+=rv*w1.w;
    }
#pragma unroll
    for (int off = 16; off > 0; off >>= 1)
#pragma unroll
        for (int m = 0; m < 8; m++) acc[m] += __shfl_xor_sync(0xffffffffu, acc[m], off);
    float mx = -1e30f;
#pragma unroll
    for (int m = 0; m < 8; m++) { acc[m] += br2[m]; mx = fmaxf(mx, acc[m]); }
    float s = 0.f;
#pragma unroll
    for (int m = 0; m < 8; m++) { acc[m] = expf(acc[m] - mx); s += acc[m]; }
    float inv = 1.f / s;
    if (lane < 8) probs[(size_t)idx * 8 + lane] = acc[lane] * inv;
}

// ---------------- launch -----------------------------------------------------
extern "C" void kernel_launch(void* const* d_in, const int* in_sizes, int n_in,
                              void* d_out, int out_size) {
    (void)in_sizes; (void)n_in; (void)out_size;
    const float* x     = (const float*)d_in[0];
    const float* W_in  = (const float*)d_in[1];
    const float* b_in  = (const float*)d_in[2];
    const float* W_mod = (const float*)d_in[3];
    const float* b_mod = (const float*)d_in[4];
    const float* Wr1   = (const float*)d_in[5];
    const float* br1   = (const float*)d_in[6];
    const float* Wr2   = (const float*)d_in[7];
    const float* br2   = (const float*)d_in[8];
    const float* Wc    = (const float*)d_in[9];
    const float* bc    = (const float*)d_in[10];
    const float* W_out = (const float*)d_in[11];
    const float* b_out = (const float*)d_in[12];
    float* out = (float*)d_out;

    float *h, *r, *probs, *wr1c;
    __nv_bfloat16 *ahA, *alA, *ahB, *alB, *wh, *wl;
    cudaGetSymbolAddress((void**)&h,     g_h);
    cudaGetSymbolAddress((void**)&r,     g_r);
    cudaGetSymbolAddress((void**)&probs, g_probs);
    cudaGetSymbolAddress((void**)&wr1c,  g_wr1c);
    cudaGetSymbolAddress((void**)&ahA,   g_ahA);
    cudaGetSymbolAddress((void**)&alA,   g_alA);
    cudaGetSymbolAddress((void**)&ahB,   g_ahB);
    cudaGetSymbolAddress((void**)&alB,   g_alB);
    cudaGetSymbolAddress((void**)&wh,    g_wh);
    cudaGetSymbolAddress((void**)&wl,    g_wl);

    cudaFuncSetAttribute(expert_pl, cudaFuncAttributeMaxDynamicSharedMemorySize, SMEM_TOT);

    dim3 blk(256);
    dim3 eblk(ETHR);
    dim3 gH(Hn / 128, Bn / 128);
    dim3 gO(OUTn / 128, Bn / 128);
    dim3 gW(Hn / 32, Hn / 32, Mn);
    dim3 gE(Hn / 128, Bn / 128);

    // 0. one-time operand prep
    prep_wr1c<<<Hn, 256>>>(Wr1, Wc, bc, wr1c);
    wconv<<<gW, dim3(32, 8)>>>(W_mod, wh, wl);
    // 1. h = x @ W_in + b_in (also "orig")
    gemm_kernel<0><<<gH, blk>>>(x, INn, W_in, Hn, b_in, h, Hn, INn);
    // 2. router features (all cycles folded) + probs
    gemm_kernel<1><<<gH, blk>>>(h, Hn, wr1c, Hn, br1, r, Hn, Hn);
    probs_kernel<<<(Bn * CYC) / 8, 256>>>(r, Wr2, br2, probs);
    // 3. split h into bf16 planes once; experts ping-pong planes themselves
    hconv<<<(Bn * Hn) / (256 * 4), 256>>>((const float4*)h, (uint2*)ahA, (uint2*)alA);
    expert_pl<<<gE, eblk, SMEM_TOT>>>(ahA, alA, wh, wl, ahB, alB, h, 0, b_mod, probs, 0);
    expert_pl<<<gE, eblk, SMEM_TOT>>>(ahB, alB, wh, wl, ahA, alA, h, 0, b_mod, probs, 1);
    expert_pl<<<gE, eblk, SMEM_TOT>>>(ahA, alA, wh, wl, ahB, alB, h, 0, b_mod, probs, 2);
    expert_pl<<<gE, eblk, SMEM_TOT>>>(ahB, alB, wh, wl, ahA, alA, h, 1, b_mod, probs, 3);
    // 4. out = h @ W_out + b_out
    gemm_kernel<0><<<gO, blk>>>(h, Hn, W_out, OUTn, b_out, out, OUTn, Hn);
}